// round 14
// baseline (speedup 1.0000x reference)
#include <cuda_runtime.h>
#include <cuda_bf16.h>
#include <cstdint>

#define C_CLASSES  6625
#define ROW_BYTES  (C_CLASSES * 4)      // 26500, only 4B-aligned
#define CP_BYTES   26496                // 1656*16: bulk-copy size, always in-bounds
#define BUF_F      (CP_BYTES / 4)       // 6624 floats per buffer
#define D_DIM      96
#define NTHREADS   256
#define NWARPS     (NTHREADS / 32)
#define GRID       608                  // 152 SMs * 4 CTAs (persistent)
#define EPSV       1e-7f
#define INFV       1e11f

// Cross-CTA accumulator + completion counter (zero at module load; the
// finalizing CTA resets them so every graph replay starts clean).
__device__ float    g_acc;
__device__ unsigned g_done;

// Tournament compare: independent fmax tree, one dependent compare vs best;
// x,y,z,w tested in order keeps first-occurrence within the quad.
__device__ __forceinline__ void cmp4t(float4 q, int base, float& best, int& bidx) {
    float m = fmaxf(fmaxf(q.x, q.y), fmaxf(q.z, q.w));
    if (m > best) {
        best = m;
        bidx = (q.x == m) ? base
             : (q.y == m) ? base + 1
             : (q.z == m) ? base + 2
             :              base + 3;
    }
}

__device__ __forceinline__ void mbar_wait_acq(uint32_t mb, uint32_t parity) {
    uint32_t done = 0;
    while (!done) {
        asm volatile(
            "{\n\t.reg .pred p;\n\t"
            "mbarrier.try_wait.parity.acquire.cta.shared::cta.b64 p, [%1], %2, 0x989680;\n\t"
            "selp.b32 %0, 1, 0, p;\n\t}"
            : "=r"(done) : "r"(mb), "r"(parity) : "memory");
    }
}

__global__ __launch_bounds__(NTHREADS, 4)
void center_loss_kernel(const float* __restrict__ features,  // [N, 96]
                        const float* __restrict__ predicts,  // [N, 6625]
                        const float* __restrict__ centers,   // [6625, 96]
                        float* __restrict__ out,
                        int N)
{
    extern __shared__ float dynbuf[];                    // 2 * BUF_F floats
    __shared__ alignas(8) unsigned long long mbar[2];
    __shared__ float swv[NWARPS];
    __shared__ int   swi[NWARPS];
    __shared__ int   slabel;

    const int tid = threadIdx.x;
    const uint32_t mb0  = (uint32_t)__cvta_generic_to_shared(&mbar[0]);
    const uint32_t mb1  = (uint32_t)__cvta_generic_to_shared(&mbar[1]);
    const uint32_t dst0 = (uint32_t)__cvta_generic_to_shared(dynbuf);
    const uint32_t dst1 = (uint32_t)__cvta_generic_to_shared(dynbuf + BUF_F);

    if (tid == 0) {
        asm volatile("mbarrier.init.shared.b64 [%0], 1;" :: "r"(mb0) : "memory");
        asm volatile("mbarrier.init.shared.b64 [%0], 1;" :: "r"(mb1) : "memory");
    }
    __syncthreads();

    // Issue the first row's bulk copy into buffer 0.
    const int n0 = blockIdx.x;
    if (tid == 0 && n0 < N) {
        uintptr_t ra  = (uintptr_t)predicts + (size_t)n0 * ROW_BYTES;
        uintptr_t src = ra & ~(uintptr_t)15;
        asm volatile("mbarrier.arrive.expect_tx.shared.b64 _, [%0], %1;"
                     :: "r"(mb0), "r"((uint32_t)CP_BYTES) : "memory");
        asm volatile("cp.async.bulk.shared::cta.global.mbarrier::complete_tx::bytes "
                     "[%0], [%1], %2, [%3];"
                     :: "r"(dst0), "l"((const void*)src),
                        "r"((uint32_t)CP_BYTES), "r"(mb0) : "memory");
    }

    float acc  = 0.0f;     // per-CTA loss accumulation (valid at tid 0)
    int   cur  = 0;
    int   ph0  = 0, ph1 = 0;

    for (int n = n0; n < N; n += GRID) {
        const uintptr_t row_addr = (uintptr_t)predicts + (size_t)n * ROW_BYTES;
        const int shift   = (int)((row_addr & 15) >> 2);  // 0..3
        const int n_avail = BUF_F - shift;                // staged elements

        // Gmem tail (last shift+1 elems) fetched while the copy is in flight.
        float gval = -3.402823466e38f;
        const int gc = n_avail + tid;
        if (tid < C_CLASSES - n_avail)
            gval = __ldg((const float*)row_addr + gc);

        // Wait for this row's staged data.
        if (cur == 0) { mbar_wait_acq(mb0, (uint32_t)ph0); ph0 ^= 1; }
        else          { mbar_wait_acq(mb1, (uint32_t)ph1); ph1 ^= 1; }

        // Immediately refill the OTHER buffer with the next row (its readers
        // all passed last iteration's __syncthreads, so it is free).
        const int n_next = n + GRID;
        if (tid == 0 && n_next < N) {
            uintptr_t ra2  = (uintptr_t)predicts + (size_t)n_next * ROW_BYTES;
            uintptr_t src2 = ra2 & ~(uintptr_t)15;
            const uint32_t mbn  = cur ? mb0 : mb1;
            const uint32_t dstn = cur ? dst0 : dst1;
            asm volatile("mbarrier.arrive.expect_tx.shared.b64 _, [%0], %1;"
                         :: "r"(mbn), "r"((uint32_t)CP_BYTES) : "memory");
            asm volatile("cp.async.bulk.shared::cta.global.mbarrier::complete_tx::bytes "
                         "[%0], [%1], %2, [%3];"
                         :: "r"(dstn), "l"((const void*)src2),
                            "r"((uint32_t)CP_BYTES), "r"(mbn) : "memory");
        }

        // ── scan the staged row from smem ──
        const float* rowf = dynbuf + cur * BUF_F + shift;  // rowf[c] == row[c]
        const int q   = (4 - shift) & 3;                   // align prologue
        const int nvv = (n_avail - q) >> 2;                // float4 count
        const float4* vrow = (const float4*)(rowf + q);

        float best = -3.402823466e38f;
        int   bidx = C_CLASSES;

        #pragma unroll
        for (int i = 0; i < 7; i++) {                      // ceil(nvv/256) == 7
            int v = tid + i * NTHREADS;
            if (v < nvv) cmp4t(vrow[v], q + (v << 2), best, bidx);
        }
        if (tid < q) {                                     // lowest indices
            float v = rowf[tid];
            if (v > best || (v == best && tid < bidx)) { best = v; bidx = tid; }
        }
        {                                                  // staged tail
            int c = q + (nvv << 2) + tid;
            if (c < n_avail) {
                float v = rowf[c];
                if (v > best) { best = v; bidx = c; }
            }
        }
        if (tid < C_CLASSES - n_avail && gval > best) { best = gval; bidx = gc; }

        // Warp (val, idx) reduce, min-idx tie-break (first occurrence).
        #pragma unroll
        for (int off = 16; off > 0; off >>= 1) {
            float ov = __shfl_down_sync(0xffffffffu, best, off);
            int   oi = __shfl_down_sync(0xffffffffu, bidx, off);
            if (ov > best || (ov == best && oi < bidx)) { best = ov; bidx = oi; }
        }
        if ((tid & 31) == 0) { swv[tid >> 5] = best; swi[tid >> 5] = bidx; }
        __syncthreads();
        if (tid == 0) {
            float bv = swv[0]; int bi = swi[0];
            #pragma unroll
            for (int w = 1; w < NWARPS; w++)
                if (swv[w] > bv || (swv[w] == bv && swi[w] < bi)) { bv = swv[w]; bi = swi[w]; }
            slabel = bi;
        }
        __syncthreads();

        // Distance over D=96: warp 0 only (others may proceed to next wait).
        if (tid < 32) {
            const int label = slabel;
            float part = 0.0f;
            if (tid < D_DIM / 4) {
                float4 f = __ldg((const float4*)(features + (size_t)n * D_DIM) + tid);
                float4 c = __ldg((const float4*)(centers + (size_t)label * D_DIM) + tid);
                float dx = f.x - c.x, dy = f.y - c.y, dz = f.z - c.z, dw = f.w - c.w;
                part = dx * dx + dy * dy + dz * dz + dw * dw;
            }
            #pragma unroll
            for (int off = 16; off > 0; off >>= 1)
                part += __shfl_down_sync(0xffffffffu, part, off);
            if (tid == 0)
                acc += fminf(fmaxf(part, EPSV), INFV) / (float)N;
        }

        cur ^= 1;
    }

    // ── finalize: one atomic per CTA; last CTA writes out and resets ──
    if (tid == 0) {
        atomicAdd(&g_acc, acc);
        __threadfence();
        unsigned old = atomicAdd(&g_done, 1u);
        if (old == gridDim.x - 1) {
            float total = atomicAdd(&g_acc, 0.0f);   // read via L2 atomic
            out[0] = total + (float)(C_CLASSES - 1) * EPSV;
            atomicExch(&g_acc, 0.0f);                // reset for next replay
            atomicExch(&g_done, 0u);
        }
    }
}

extern "C" void kernel_launch(void* const* d_in, const int* in_sizes, int n_in,
                              void* d_out, int out_size) {
    const float* features = (const float*)d_in[0];  // [B,T,D] fp32
    const float* predicts = (const float*)d_in[1];  // [B,T,C] fp32
    const float* centers  = (const float*)d_in[2];  // [C,D]   fp32
    float* out = (float*)d_out;

    const int N = in_sizes[0] / D_DIM;  // B*T = 8192
    const int dyn_smem = 2 * CP_BYTES;  // 52992 B: two row buffers

    static int configured = 0;
    if (!configured) {
        cudaFuncSetAttribute(center_loss_kernel,
                             cudaFuncAttributeMaxDynamicSharedMemorySize, dyn_smem);
        configured = 1;
    }

    center_loss_kernel<<<GRID, NTHREADS, dyn_smem>>>(features, predicts, centers, out, N);
}